// round 1
// baseline (speedup 1.0000x reference)
#include <cuda_runtime.h>
#include <math.h>

#define Bb 4
#define Ss 2048
#define Dd 1024
#define Hh 16
#define DK 64
#define Mm (Bb*Ss)

// Scratch (no cudaMalloc allowed)
__device__ float g_q[Bb*Hh*Ss*DK];
__device__ float g_k[Bb*Hh*Ss*DK];
__device__ float g_v[Bb*Hh*Ss*DK];
__device__ float g_att[Bb*Ss*Dd];

// ---------------------------------------------------------------------------
// QKV projection: out[m][n] = sum_k x[m][k] * W[n][k]  (NT GEMM)
// Epilogue scatters into [b][h][s][j] layout for attention.
// grid(128, 16, 3), block(16,16)
// ---------------------------------------------------------------------------
__global__ void qkv_gemm(const float* __restrict__ x, const float* __restrict__ wq,
                         const float* __restrict__ wk, const float* __restrict__ wv)
{
    __shared__ float As[64][17];
    __shared__ float Bs[64][17];
    const float* W = (blockIdx.z == 0) ? wq : ((blockIdx.z == 1) ? wk : wv);
    float* dst = (blockIdx.z == 0) ? g_q : ((blockIdx.z == 1) ? g_k : g_v);

    const int m0 = blockIdx.x * 64, n0 = blockIdx.y * 64;
    const int tx = threadIdx.x, ty = threadIdx.y;
    const int tid = ty * 16 + tx;

    float acc[4][4] = {};

    for (int kt = 0; kt < Dd; kt += 16) {
#pragma unroll
        for (int l = 0; l < 4; l++) {
            int idx = tid + l * 256;
            int rr = idx >> 4, cc = idx & 15;
            As[rr][cc] = x[(size_t)(m0 + rr) * Dd + kt + cc];
            Bs[rr][cc] = W[(size_t)(n0 + rr) * Dd + kt + cc];
        }
        __syncthreads();
#pragma unroll
        for (int kk = 0; kk < 16; kk++) {
            float a[4], bv[4];
#pragma unroll
            for (int i = 0; i < 4; i++) a[i] = As[ty * 4 + i][kk];
#pragma unroll
            for (int j = 0; j < 4; j++) bv[j] = Bs[tx * 4 + j][kk];
#pragma unroll
            for (int i = 0; i < 4; i++)
#pragma unroll
                for (int j = 0; j < 4; j++) acc[i][j] += a[i] * bv[j];
        }
        __syncthreads();
    }

#pragma unroll
    for (int i = 0; i < 4; i++) {
        int m = m0 + ty * 4 + i;
        int b = m / Ss, s = m % Ss;
#pragma unroll
        for (int j = 0; j < 4; j++) {
            int n = n0 + tx * 4 + j;
            int h = n >> 6, jj = n & 63;
            dst[(((size_t)(b * Hh + h)) * Ss + s) * DK + jj] = acc[i][j];
        }
    }
}

// ---------------------------------------------------------------------------
// RoPE in-place on [b][h][s][j] tensor (interleaved even/odd pairs).
// which: 0 -> g_q, 1 -> g_k
// ---------------------------------------------------------------------------
__global__ void rope_kernel(int which)
{
    const int TOTP = Bb * Hh * Ss * (DK / 2);
    int i = blockIdx.x * blockDim.x + threadIdx.x;
    if (i >= TOTP) return;
    float* t = which ? g_k : g_q;
    int j2 = i & 31;
    int s = (i >> 5) & (Ss - 1);
    int bh = i >> 16;           // 5 (pair) + 11 (seq) bits
    float* p = t + ((size_t)bh * Ss + s) * DK + 2 * j2;
    // inv_freq = theta^(-2*j2/64), theta = 10000
    float freq = expf(-(2.0f * j2 / 64.0f) * 9.210340371976184f); // ln(1e4)
    float ang = (float)s * freq;
    float sn, cs;
    sincosf(ang, &sn, &cs);
    float x1 = p[0], x2 = p[1];
    p[0] = x1 * cs - x2 * sn;
    p[1] = x1 * sn + x2 * cs;
}

// ---------------------------------------------------------------------------
// Causal flash attention, 64-row Q tile, 64-col KV tiles, online softmax.
// grid(32, 16, 4) = (qtile, h, b), block(16,16).
// Dynamic smem: Qs[64*64] | KP[64*65] (K transposed, reused as P) | Vs[64*64]
// ---------------------------------------------------------------------------
__global__ void flash_attn()
{
    extern __shared__ float sm[];
    float* Qs = sm;                 // Qs[r*64 + d]
    float* KP = sm + 4096;          // K: KP[d*65 + c]; later P: KP[r*65 + c]
    float* Vs = sm + 4096 + 64 * 65;// Vs[c*64 + d]

    const int qi = blockIdx.x, h = blockIdx.y, b = blockIdx.z;
    const int tx = threadIdx.x, ty = threadIdx.y;
    const int tid = ty * 16 + tx;
    const int r0 = ty * 4, c0 = tx * 4;
    const float scale = 0.125f; // 1/sqrt(64)

    const float* Qg = g_q + (((size_t)(b * Hh + h)) * Ss + qi * 64) * DK;
    for (int idx = tid; idx < 64 * 64; idx += 256) Qs[idx] = Qg[idx];

    float acc[4][4] = {};
    float m_i[4], l_i[4];
#pragma unroll
    for (int i = 0; i < 4; i++) { m_i[i] = -INFINITY; l_i[i] = 0.0f; }
    __syncthreads();

    for (int j = 0; j <= qi; ++j) {
        const float* Kg = g_k + (((size_t)(b * Hh + h)) * Ss + j * 64) * DK;
        const float* Vg = g_v + (((size_t)(b * Hh + h)) * Ss + j * 64) * DK;
        for (int idx = tid; idx < 4096; idx += 256) {
            int c = idx >> 6, d = idx & 63;
            KP[d * 65 + c] = Kg[idx];   // transposed, pad-65: conflict-free
            Vs[idx] = Vg[idx];
        }
        __syncthreads();

        // scores: s[i][j] = sum_d Q[r][d] * K[c][d]
        float s[4][4] = {};
#pragma unroll 16
        for (int kk = 0; kk < 64; kk++) {
            float a[4], bv[4];
#pragma unroll
            for (int i = 0; i < 4; i++) a[i] = Qs[(r0 + i) * 64 + kk];
#pragma unroll
            for (int jj = 0; jj < 4; jj++) bv[jj] = KP[kk * 65 + c0 + jj];
#pragma unroll
            for (int i = 0; i < 4; i++)
#pragma unroll
                for (int jj = 0; jj < 4; jj++) s[i][jj] += a[i] * bv[jj];
        }
        __syncthreads();  // everyone done reading K before P overwrite

        const bool diag = (j == qi);
#pragma unroll
        for (int i = 0; i < 4; i++) {
            int rg = qi * 64 + r0 + i;
#pragma unroll
            for (int jj = 0; jj < 4; jj++) {
                int cg = j * 64 + c0 + jj;
                s[i][jj] = (diag && cg > rg) ? -INFINITY : s[i][jj] * scale;
            }
            // row max across 16 tx-lanes (contiguous 16-lane groups in warp)
            float tm = fmaxf(fmaxf(s[i][0], s[i][1]), fmaxf(s[i][2], s[i][3]));
#pragma unroll
            for (int off = 8; off >= 1; off >>= 1)
                tm = fmaxf(tm, __shfl_xor_sync(0xffffffffu, tm, off));
            float mnew = fmaxf(m_i[i], tm);
            float rsum = 0.0f;
#pragma unroll
            for (int jj = 0; jj < 4; jj++) {
                float p = expf(s[i][jj] - mnew);
                s[i][jj] = p;
                rsum += p;
            }
#pragma unroll
            for (int off = 8; off >= 1; off >>= 1)
                rsum += __shfl_xor_sync(0xffffffffu, rsum, off);
            float fac = expf(m_i[i] - mnew);
            l_i[i] = l_i[i] * fac + rsum;
            m_i[i] = mnew;
#pragma unroll
            for (int jj = 0; jj < 4; jj++) acc[i][jj] *= fac;
            // publish P row chunk
#pragma unroll
            for (int jj = 0; jj < 4; jj++)
                KP[(r0 + i) * 65 + c0 + jj] = s[i][jj];
        }
        __syncthreads();

        // O += P @ V
#pragma unroll 8
        for (int c = 0; c < 64; c++) {
            float v[4];
#pragma unroll
            for (int jj = 0; jj < 4; jj++) v[jj] = Vs[c * 64 + c0 + jj];
#pragma unroll
            for (int i = 0; i < 4; i++) {
                float pr = KP[(r0 + i) * 65 + c];
#pragma unroll
                for (int jj = 0; jj < 4; jj++) acc[i][jj] += pr * v[jj];
            }
        }
        __syncthreads();  // before next tile overwrites KP/Vs
    }

    // normalize + write [b][s][h][j] (== contiguous B,S,D)
#pragma unroll
    for (int i = 0; i < 4; i++) {
        float inv = 1.0f / l_i[i];
        int s = qi * 64 + r0 + i;
#pragma unroll
        for (int jj = 0; jj < 4; jj++) {
            g_att[(((size_t)b * Ss + s) * Hh + h) * DK + c0 + jj] = acc[i][jj] * inv;
        }
    }
}

// ---------------------------------------------------------------------------
// Output projection: out[m][n] = sum_k att[m][k] * wo[n][k]
// grid(128, 16), block(16,16)
// ---------------------------------------------------------------------------
__global__ void out_gemm(const float* __restrict__ wo, float* __restrict__ C)
{
    __shared__ float As[64][17];
    __shared__ float Bs[64][17];
    const int m0 = blockIdx.x * 64, n0 = blockIdx.y * 64;
    const int tx = threadIdx.x, ty = threadIdx.y;
    const int tid = ty * 16 + tx;

    float acc[4][4] = {};
    for (int kt = 0; kt < Dd; kt += 16) {
#pragma unroll
        for (int l = 0; l < 4; l++) {
            int idx = tid + l * 256;
            int rr = idx >> 4, cc = idx & 15;
            As[rr][cc] = g_att[(size_t)(m0 + rr) * Dd + kt + cc];
            Bs[rr][cc] = wo[(size_t)(n0 + rr) * Dd + kt + cc];
        }
        __syncthreads();
#pragma unroll
        for (int kk = 0; kk < 16; kk++) {
            float a[4], bv[4];
#pragma unroll
            for (int i = 0; i < 4; i++) a[i] = As[ty * 4 + i][kk];
#pragma unroll
            for (int j = 0; j < 4; j++) bv[j] = Bs[tx * 4 + j][kk];
#pragma unroll
            for (int i = 0; i < 4; i++)
#pragma unroll
                for (int j = 0; j < 4; j++) acc[i][j] += a[i] * bv[j];
        }
        __syncthreads();
    }
#pragma unroll
    for (int i = 0; i < 4; i++) {
        int m = m0 + ty * 4 + i;
#pragma unroll
        for (int j = 0; j < 4; j++) {
            C[(size_t)m * Dd + n0 + tx * 4 + j] = acc[i][j];
        }
    }
}

// ---------------------------------------------------------------------------
extern "C" void kernel_launch(void* const* d_in, const int* in_sizes, int n_in,
                              void* d_out, int out_size)
{
    const float* x  = (const float*)d_in[0];
    const float* wq = (const float*)d_in[1];
    const float* wk = (const float*)d_in[2];
    const float* wv = (const float*)d_in[3];
    const float* wo = (const float*)d_in[4];
    float* out = (float*)d_out;

    (void)in_sizes; (void)n_in; (void)out_size;

    const int FLASH_SMEM = (64 * 64 + 64 * 65 + 64 * 64) * (int)sizeof(float); // 49408
    cudaFuncSetAttribute(flash_attn, cudaFuncAttributeMaxDynamicSharedMemorySize, FLASH_SMEM);

    dim3 blk(16, 16);

    // 1) QKV projections with head-layout scatter
    qkv_gemm<<<dim3(Mm / 64, Dd / 64, 3), blk>>>(x, wq, wk, wv);

    // 2) RoPE on q and k
    {
        const int TOTP = Bb * Hh * Ss * (DK / 2);
        rope_kernel<<<TOTP / 256, 256>>>(0);
        rope_kernel<<<TOTP / 256, 256>>>(1);
    }

    // 3) causal flash attention
    flash_attn<<<dim3(Ss / 64, Hh, Bb), blk, FLASH_SMEM>>>();

    // 4) output projection
    out_gemm<<<dim3(Mm / 64, Dd / 64), blk>>>(wo, out);
}

// round 6
// speedup vs baseline: 2.9941x; 2.9941x over previous
#include <cuda_runtime.h>
#include <cuda_bf16.h>
#include <math.h>

#define Bb 4
#define Ss 2048
#define Dd 1024
#define Hh 16
#define DK 64
#define Mm (Bb*Ss)

// Scratch (no cudaMalloc allowed)
__device__ float g_q[Bb*Hh*Ss*DK];    // [b][h][s][d]
__device__ float g_k[Bb*Hh*Ss*DK];    // [b][h][s][d]
__device__ float g_v[Bb*Hh*Ss*DK];    // [b][h][d][s]  (transposed for PV MMA)
__device__ float g_att[Bb*Ss*Dd];     // [b][s][h*64+d]

// ---------------------------------------------------------------------------
// bf16 m16n8k16 MMA wrapper
// ---------------------------------------------------------------------------
__device__ __forceinline__ void mma16816(float* c, const unsigned* a, const unsigned* b)
{
    asm volatile(
        "mma.sync.aligned.m16n8k16.row.col.f32.bf16.bf16.f32 "
        "{%0,%1,%2,%3}, {%4,%5,%6,%7}, {%8,%9}, {%0,%1,%2,%3};\n"
        : "+f"(c[0]), "+f"(c[1]), "+f"(c[2]), "+f"(c[3])
        : "r"(a[0]), "r"(a[1]), "r"(a[2]), "r"(a[3]), "r"(b[0]), "r"(b[1]));
}

// split x,y into bf16 hi pair + bf16 lo pair (packed b32 each, x in low half)
__device__ __forceinline__ void splitpack(float x, float y, unsigned& hi, unsigned& lo)
{
    __nv_bfloat162 h2 = __floats2bfloat162_rn(x, y);
    float hx = __bfloat162float(h2.x), hy = __bfloat162float(h2.y);
    __nv_bfloat162 l2 = __floats2bfloat162_rn(x - hx, y - hy);
    hi = *reinterpret_cast<unsigned*>(&h2);
    lo = *reinterpret_cast<unsigned*>(&l2);
}

// ---------------------------------------------------------------------------
// Split-precision bf16 tensor-core GEMM: C[m][n] = sum_k A[m][k] * W[n][k]
// C ≈ Ah*Wh + Al*Wh + Ah*Wl.  Block 128x128, BK=32, 8 warps, warp tile 32x64.
// mode 0: QKV. z selects W/dst. Q,K scatter to [b][h][s][d]; V to [b][h][d][s].
// mode 1: out-proj (A = g_att, selected in device code), linear epilogue.
// ---------------------------------------------------------------------------
#define LDS_STRIDE 36   // halves per row (32 + 4 pad)

__global__ __launch_bounds__(256, 2)
void gemm_bf16s(const float* __restrict__ Ain,
                const float* __restrict__ w0, const float* __restrict__ w1,
                const float* __restrict__ w2, float* __restrict__ outp, int mode)
{
    __shared__ __nv_bfloat16 Ah[128 * LDS_STRIDE];
    __shared__ __nv_bfloat16 Al[128 * LDS_STRIDE];
    __shared__ __nv_bfloat16 Bh[128 * LDS_STRIDE];
    __shared__ __nv_bfloat16 Bl[128 * LDS_STRIDE];

    const float* A;
    const float* W;
    float* dst;
    if (mode == 0) {
        A   = Ain;
        W   = (blockIdx.z == 0) ? w0  : (blockIdx.z == 1) ? w1  : w2;
        dst = (blockIdx.z == 0) ? g_q : (blockIdx.z == 1) ? g_k : g_v;
    } else {
        A = g_att;           // device-side symbol reference
        W = w0; dst = outp;
    }

    const int m0 = blockIdx.x * 128, n0 = blockIdx.y * 128;
    const int tid = threadIdx.x;
    const int wid = tid >> 5, lane = tid & 31;
    const int wm = (wid & 3) * 32;
    const int wn = (wid >> 2) * 64;
    const int lr = lane >> 2;
    const int lk = (lane & 3) * 2;

    float acc[2][8][4];
#pragma unroll
    for (int i = 0; i < 2; i++)
#pragma unroll
        for (int j = 0; j < 8; j++)
#pragma unroll
            for (int q = 0; q < 4; q++) acc[i][j][q] = 0.0f;

    for (int kt = 0; kt < Dd; kt += 32) {
#pragma unroll
        for (int l = 0; l < 4; l++) {
            int fi = tid + l * 256;
            int row = fi >> 3, kq = fi & 7;
            float4 va = *(const float4*)&A[(size_t)(m0 + row) * Dd + kt + kq * 4];
            float4 vb = *(const float4*)&W[(size_t)(n0 + row) * Dd + kt + kq * 4];
            int off = row * LDS_STRIDE + kq * 4;
            unsigned h0, l0, h1, l1;
            splitpack(va.x, va.y, h0, l0);
            splitpack(va.z, va.w, h1, l1);
            *(unsigned*)&Ah[off]     = h0;  *(unsigned*)&Ah[off + 2] = h1;
            *(unsigned*)&Al[off]     = l0;  *(unsigned*)&Al[off + 2] = l1;
            splitpack(vb.x, vb.y, h0, l0);
            splitpack(vb.z, vb.w, h1, l1);
            *(unsigned*)&Bh[off]     = h0;  *(unsigned*)&Bh[off + 2] = h1;
            *(unsigned*)&Bl[off]     = l0;  *(unsigned*)&Bl[off + 2] = l1;
        }
        __syncthreads();

#pragma unroll
        for (int kc = 0; kc < 32; kc += 16) {
            unsigned ah[2][4], al[2][4];
#pragma unroll
            for (int mt = 0; mt < 2; mt++) {
                int r = wm + mt * 16 + lr;
                int kb = kc + lk;
                ah[mt][0] = *(const unsigned*)&Ah[r * LDS_STRIDE + kb];
                ah[mt][1] = *(const unsigned*)&Ah[(r + 8) * LDS_STRIDE + kb];
                ah[mt][2] = *(const unsigned*)&Ah[r * LDS_STRIDE + kb + 8];
                ah[mt][3] = *(const unsigned*)&Ah[(r + 8) * LDS_STRIDE + kb + 8];
                al[mt][0] = *(const unsigned*)&Al[r * LDS_STRIDE + kb];
                al[mt][1] = *(const unsigned*)&Al[(r + 8) * LDS_STRIDE + kb];
                al[mt][2] = *(const unsigned*)&Al[r * LDS_STRIDE + kb + 8];
                al[mt][3] = *(const unsigned*)&Al[(r + 8) * LDS_STRIDE + kb + 8];
            }
#pragma unroll
            for (int nt = 0; nt < 8; nt++) {
                int nr = wn + nt * 8 + lr;
                int kb = kc + lk;
                unsigned bh[2], bl[2];
                bh[0] = *(const unsigned*)&Bh[nr * LDS_STRIDE + kb];
                bh[1] = *(const unsigned*)&Bh[nr * LDS_STRIDE + kb + 8];
                bl[0] = *(const unsigned*)&Bl[nr * LDS_STRIDE + kb];
                bl[1] = *(const unsigned*)&Bl[nr * LDS_STRIDE + kb + 8];
#pragma unroll
                for (int mt = 0; mt < 2; mt++) {
                    mma16816(acc[mt][nt], ah[mt], bh);
                    mma16816(acc[mt][nt], al[mt], bh);
                    mma16816(acc[mt][nt], ah[mt], bl);
                }
            }
        }
        __syncthreads();
    }

    // ---- epilogue ----
    const bool vtrans = (mode == 0) && (blockIdx.z == 2);
#pragma unroll
    for (int mt = 0; mt < 2; mt++) {
        int r1 = m0 + wm + mt * 16 + lr;
        int r2 = r1 + 8;
#pragma unroll
        for (int nt = 0; nt < 8; nt++) {
            int c = n0 + wn + nt * 8 + lk;
            if (mode == 0) {
                int b1 = r1 / Ss, s1 = r1 % Ss;
                int b2 = r2 / Ss, s2 = r2 % Ss;
                int h = c >> 6, jj = c & 63;
                if (vtrans) {
                    float* base1 = dst + ((size_t)(b1 * Hh + h) * DK) * Ss;
                    float* base2 = dst + ((size_t)(b2 * Hh + h) * DK) * Ss;
                    base1[(size_t)jj * Ss + s1]       = acc[mt][nt][0];
                    base1[(size_t)(jj + 1) * Ss + s1] = acc[mt][nt][1];
                    base2[(size_t)jj * Ss + s2]       = acc[mt][nt][2];
                    base2[(size_t)(jj + 1) * Ss + s2] = acc[mt][nt][3];
                } else {
                    float* p1 = dst + (((size_t)(b1 * Hh + h)) * Ss + s1) * DK + jj;
                    float* p2 = dst + (((size_t)(b2 * Hh + h)) * Ss + s2) * DK + jj;
                    p1[0] = acc[mt][nt][0]; p1[1] = acc[mt][nt][1];
                    p2[0] = acc[mt][nt][2]; p2[1] = acc[mt][nt][3];
                }
            } else {
                float* p1 = dst + (size_t)r1 * Dd + c;
                float* p2 = dst + (size_t)r2 * Dd + c;
                p1[0] = acc[mt][nt][0]; p1[1] = acc[mt][nt][1];
                p2[0] = acc[mt][nt][2]; p2[1] = acc[mt][nt][3];
            }
        }
    }
}

// ---------------------------------------------------------------------------
// RoPE in-place on q AND k ([b][h][s][d]) in a single launch.
// ---------------------------------------------------------------------------
__global__ void rope_kernel()
{
    const int TOTP = Bb * Hh * Ss * (DK / 2);   // per tensor
    int i = blockIdx.x * blockDim.x + threadIdx.x;
    float* t = (i < TOTP) ? g_q : g_k;
    if (i >= TOTP) i -= TOTP;
    int j2 = i & 31;
    int s = (i >> 5) & (Ss - 1);
    int bh = i >> 16;
    float* p = t + ((size_t)bh * Ss + s) * DK + 2 * j2;
    float freq = expf(-(2.0f * j2 / 64.0f) * 9.210340371976184f);
    float ang = (float)s * freq;
    float sn, cs;
    sincosf(ang, &sn, &cs);
    float x1 = p[0], x2 = p[1];
    p[0] = x1 * cs - x2 * sn;
    p[1] = x1 * sn + x2 * cs;
}

// ---------------------------------------------------------------------------
// Causal flash attention, tensor cores, split bf16, base-2 online softmax.
// grid(32, 16, 4) = (qtile, h, b); block(128) = 4 warps, each 16 Q rows.
// S = Q K^T via m16n8k16 (3-term split); P stays in registers (C-frag == A-frag);
// O += P V (3-term split) with V pre-transposed [d][s] in gmem.
// ---------------------------------------------------------------------------
#define FST 72   // smem stride in halves (64 + 8 pad) -> conflict-free frags

__global__ __launch_bounds__(128)
void flash_attn_mma()
{
    __shared__ __nv_bfloat16 Ksh[64 * FST];
    __shared__ __nv_bfloat16 Ksl[64 * FST];
    __shared__ __nv_bfloat16 Vsh[64 * FST];
    __shared__ __nv_bfloat16 Vsl[64 * FST];

    const int qi = blockIdx.x, h = blockIdx.y, b = blockIdx.z;
    const int tid = threadIdx.x, wid = tid >> 5, lane = tid & 31;
    const int lr = lane >> 2, lk2 = (lane & 3) * 2;
    const int wm = wid * 16;
    const int bh = b * Hh + h;
    const float sc = 0.18033688011112043f;   // (1/sqrt(64)) * log2(e)

    // ---- Q fragments (held in registers for whole block) ----
    unsigned qh[4][4], ql[4][4];
    {
        const float* Qg = g_q + ((size_t)bh * Ss + qi * 64) * DK;
        int r0 = wm + lr, r1 = r0 + 8;
#pragma unroll
        for (int kc = 0; kc < 4; kc++) {
            int d0 = kc * 16 + lk2, d2 = d0 + 8;
            float2 q00 = *(const float2*)&Qg[r0 * DK + d0];
            float2 q10 = *(const float2*)&Qg[r1 * DK + d0];
            float2 q01 = *(const float2*)&Qg[r0 * DK + d2];
            float2 q11 = *(const float2*)&Qg[r1 * DK + d2];
            splitpack(q00.x, q00.y, qh[kc][0], ql[kc][0]);
            splitpack(q10.x, q10.y, qh[kc][1], ql[kc][1]);
            splitpack(q01.x, q01.y, qh[kc][2], ql[kc][2]);
            splitpack(q11.x, q11.y, qh[kc][3], ql[kc][3]);
        }
    }

    float Oa[8][4];
#pragma unroll
    for (int nt = 0; nt < 8; nt++)
#pragma unroll
        for (int q = 0; q < 4; q++) Oa[nt][q] = 0.0f;
    float m0 = -INFINITY, m1 = -INFINITY, l0 = 0.0f, l1 = 0.0f;

    const float* Kg = g_k + ((size_t)bh * Ss) * DK;
    const float* Vg = g_v + ((size_t)bh * DK) * Ss;

    for (int j = 0; j <= qi; ++j) {
        // ---- load K tile [c][d], V tile [d][c] (gmem already transposed) ----
#pragma unroll
        for (int l = 0; l < 8; l++) {
            int fi = tid + l * 128;
            int row = fi >> 4, q4 = fi & 15;
            float4 kv = *(const float4*)&Kg[(size_t)(j * 64 + row) * DK + q4 * 4];
            unsigned h0, lo0, h1, lo1;
            splitpack(kv.x, kv.y, h0, lo0);
            splitpack(kv.z, kv.w, h1, lo1);
            int off = row * FST + q4 * 4;
            *(unsigned*)&Ksh[off]     = h0;  *(unsigned*)&Ksh[off + 2] = h1;
            *(unsigned*)&Ksl[off]     = lo0; *(unsigned*)&Ksl[off + 2] = lo1;
            float4 vv = *(const float4*)&Vg[(size_t)row * Ss + j * 64 + q4 * 4];
            splitpack(vv.x, vv.y, h0, lo0);
            splitpack(vv.z, vv.w, h1, lo1);
            *(unsigned*)&Vsh[off]     = h0;  *(unsigned*)&Vsh[off + 2] = h1;
            *(unsigned*)&Vsl[off]     = lo0; *(unsigned*)&Vsl[off + 2] = lo1;
        }
        __syncthreads();

        // ---- S = Q K^T ----
        float sa[8][4];
#pragma unroll
        for (int nt = 0; nt < 8; nt++)
#pragma unroll
            for (int q = 0; q < 4; q++) sa[nt][q] = 0.0f;

#pragma unroll
        for (int kc = 0; kc < 4; kc++) {
#pragma unroll
            for (int nt = 0; nt < 8; nt++) {
                int addr = (nt * 8 + lr) * FST + kc * 16 + lk2;
                unsigned bhK[2], blK[2];
                bhK[0] = *(const unsigned*)&Ksh[addr];
                bhK[1] = *(const unsigned*)&Ksh[addr + 8];
                blK[0] = *(const unsigned*)&Ksl[addr];
                blK[1] = *(const unsigned*)&Ksl[addr + 8];
                mma16816(sa[nt], qh[kc], bhK);
                mma16816(sa[nt], ql[kc], bhK);
                mma16816(sa[nt], qh[kc], blK);
            }
        }

        // ---- scale + causal mask ----
        const bool diag = (j == qi);
#pragma unroll
        for (int nt = 0; nt < 8; nt++) {
            int c0 = nt * 8 + lk2;
            if (diag) {
                int r0 = wm + lr, r1 = r0 + 8;
                sa[nt][0] = (c0     > r0) ? -INFINITY : sa[nt][0] * sc;
                sa[nt][1] = (c0 + 1 > r0) ? -INFINITY : sa[nt][1] * sc;
                sa[nt][2] = (c0     > r1) ? -INFINITY : sa[nt][2] * sc;
                sa[nt][3] = (c0 + 1 > r1) ? -INFINITY : sa[nt][3] * sc;
            } else {
                sa[nt][0] *= sc; sa[nt][1] *= sc;
                sa[nt][2] *= sc; sa[nt][3] *= sc;
            }
        }

        // ---- row max (2 rows per lane), reduce over 4 lanes of quad ----
        float rm0 = -INFINITY, rm1 = -INFINITY;
#pragma unroll
        for (int nt = 0; nt < 8; nt++) {
            rm0 = fmaxf(rm0, fmaxf(sa[nt][0], sa[nt][1]));
            rm1 = fmaxf(rm1, fmaxf(sa[nt][2], sa[nt][3]));
        }
        rm0 = fmaxf(rm0, __shfl_xor_sync(0xffffffffu, rm0, 1));
        rm0 = fmaxf(rm0, __shfl_xor_sync(0xffffffffu, rm0, 2));
        rm1 = fmaxf(rm1, __shfl_xor_sync(0xffffffffu, rm1, 1));
        rm1 = fmaxf(rm1, __shfl_xor_sync(0xffffffffu, rm1, 2));
        float mn0 = fmaxf(m0, rm0), mn1 = fmaxf(m1, rm1);

        // ---- exp2 + pack P (hi/lo) ----
        unsigned pha[8], phb[8], pla[8], plb[8];
        float rs0 = 0.0f, rs1 = 0.0f;
#pragma unroll
        for (int nt = 0; nt < 8; nt++) {
            float p0 = exp2f(sa[nt][0] - mn0);
            float p1 = exp2f(sa[nt][1] - mn0);
            float p2 = exp2f(sa[nt][2] - mn1);
            float p3 = exp2f(sa[nt][3] - mn1);
            rs0 += p0 + p1;
            rs1 += p2 + p3;
            splitpack(p0, p1, pha[nt], pla[nt]);
            splitpack(p2, p3, phb[nt], plb[nt]);
        }
        rs0 += __shfl_xor_sync(0xffffffffu, rs0, 1);
        rs0 += __shfl_xor_sync(0xffffffffu, rs0, 2);
        rs1 += __shfl_xor_sync(0xffffffffu, rs1, 1);
        rs1 += __shfl_xor_sync(0xffffffffu, rs1, 2);

        float f0 = exp2f(m0 - mn0), f1 = exp2f(m1 - mn1);
        l0 = l0 * f0 + rs0;
        l1 = l1 * f1 + rs1;
        m0 = mn0; m1 = mn1;
#pragma unroll
        for (int nt = 0; nt < 8; nt++) {
            Oa[nt][0] *= f0; Oa[nt][1] *= f0;
            Oa[nt][2] *= f1; Oa[nt][3] *= f1;
        }

        // ---- O += P V ----
#pragma unroll
        for (int kc = 0; kc < 4; kc++) {
            unsigned Aph[4] = { pha[2 * kc], phb[2 * kc], pha[2 * kc + 1], phb[2 * kc + 1] };
            unsigned Apl[4] = { pla[2 * kc], plb[2 * kc], pla[2 * kc + 1], plb[2 * kc + 1] };
#pragma unroll
            for (int nt = 0; nt < 8; nt++) {
                int addr = (nt * 8 + lr) * FST + kc * 16 + lk2;
                unsigned bhV[2], blV[2];
                bhV[0] = *(const unsigned*)&Vsh[addr];
                bhV[1] = *(const unsigned*)&Vsh[addr + 8];
                blV[0] = *(const unsigned*)&Vsl[addr];
                blV[1] = *(const unsigned*)&Vsl[addr + 8];
                mma16816(Oa[nt], Aph, bhV);
                mma16816(Oa[nt], Apl, bhV);
                mma16816(Oa[nt], Aph, blV);
            }
        }
        __syncthreads();   // before next iteration overwrites smem
    }

    // ---- normalize + write [b][s][h*64+d] ----
    float inv0 = 1.0f / l0, inv1 = 1.0f / l1;
    int s0 = qi * 64 + wm + lr, s1 = s0 + 8;
#pragma unroll
    for (int nt = 0; nt < 8; nt++) {
        int d = nt * 8 + lk2;
        float2 o0 = make_float2(Oa[nt][0] * inv0, Oa[nt][1] * inv0);
        float2 o1 = make_float2(Oa[nt][2] * inv1, Oa[nt][3] * inv1);
        *(float2*)&g_att[((size_t)b * Ss + s0) * Dd + h * DK + d] = o0;
        *(float2*)&g_att[((size_t)b * Ss + s1) * Dd + h * DK + d] = o1;
    }
}

// ---------------------------------------------------------------------------
extern "C" void kernel_launch(void* const* d_in, const int* in_sizes, int n_in,
                              void* d_out, int out_size)
{
    const float* x  = (const float*)d_in[0];
    const float* wq = (const float*)d_in[1];
    const float* wk = (const float*)d_in[2];
    const float* wv = (const float*)d_in[3];
    const float* wo = (const float*)d_in[4];
    float* out = (float*)d_out;

    (void)in_sizes; (void)n_in; (void)out_size;

    // 1) QKV projections (tensor cores, bf16 split); V stored transposed
    gemm_bf16s<<<dim3(Mm / 128, Dd / 128, 3), 256>>>(x, wq, wk, wv, nullptr, 0);

    // 2) RoPE on q and k (single launch)
    {
        const int TOTP = Bb * Hh * Ss * (DK / 2);
        rope_kernel<<<(2 * TOTP) / 256, 256>>>();
    }

    // 3) causal flash attention (tensor cores, split bf16)
    flash_attn_mma<<<dim3(Ss / 64, Hh, Bb), 128>>>();

    // 4) output projection (tensor cores, bf16 split; A = g_att chosen in-kernel)
    gemm_bf16s<<<dim3(Mm / 128, Dd / 128, 1), 256>>>(nullptr, wo, nullptr, nullptr, out, 1);
}